// round 2
// baseline (speedup 1.0000x reference)
#include <cuda_runtime.h>
#include <math.h>

#define NR 32768
#define DM 256
#define NLAY 3
#define NSTEP 4
#define FFD 512
#define VOC 4096
#define KL 8

// ---------------- persistent device scratch ----------------
__device__ float g_xt[NR * 4];
__device__ float g_code[NR];
__device__ int   g_gid[NR];
__device__ int   g_bin[NR];
__device__ float g_h[NR * DM];
__device__ float g_qbuf[NR * DM];
__device__ float g_attno[NR * DM];
__device__ float g_d1[NR * DM];
__device__ float g_d2[NR * FFD];
__device__ float g_kc[NLAY * NSTEP * NR * DM];
__device__ float g_vc[NLAY * NSTEP * NR * DM];
__device__ float g_z[NR * 9];
__device__ float g_zarr[NSTEP * NR];
__device__ float g_qarr[NSTEP * NR];
__device__ float g_Hc[VOC * KL];
__device__ float g_Hm1[VOC];
__device__ float g_rat[VOC * KL];
__device__ float2 g_ropetab[NSTEP * 128];
__device__ unsigned g_mm[2];
__device__ float g_pdot[128];
__device__ float g_pclip[128];
__device__ float g_pvq[128];
__device__ float g_uni;

// ---------------- helpers ----------------
__device__ __forceinline__ unsigned f2u(float f) {
    unsigned u = __float_as_uint(f);
    return (u & 0x80000000u) ? ~u : (u | 0x80000000u);
}
__device__ __forceinline__ float u2f(unsigned u) {
    u = (u & 0x80000000u) ? (u & 0x7fffffffu) : ~u;
    return __uint_as_float(u);
}

#define FMA2(d, a, b) asm("fma.rn.f32x2 %0, %1, %2, %0;" : "+l"(d) : "l"(a), "l"(b))
__device__ __forceinline__ unsigned long long dup2(float x) {
    unsigned long long r;
    asm("mov.b64 %0, {%1, %1};" : "=l"(r) : "r"(__float_as_uint(x)));
    return r;
}

// ---------------- init ----------------
__global__ void k_init(const float* __restrict__ x, const float* __restrict__ pw,
                       const float* __restrict__ pb, const float* __restrict__ rat0) {
    int n = blockIdx.x * blockDim.x + threadIdx.x;
    if (n < NR) {
        int b = n >> 10, l = n & 1023;
        const float* xb = x + (size_t)b * 32768 + l;
        #pragma unroll
        for (int j = 0; j < 4; j++) {
            float acc = pb[j];
            #pragma unroll
            for (int cz = 0; cz < 32; cz++) acc += xb[cz * 1024] * pw[j * 32 + cz];
            g_xt[n * 4 + j] = tanhf(acc);
        }
        g_code[n] = 0.f;
        g_gid[n] = 0;
    }
    if (n < VOC * KL) g_rat[n] = rat0[n];
    if (n < NSTEP * 128) {
        int pos = n >> 7, j = n & 127;
        float inv = powf(10000.f, -(float)(2 * j) / 256.f);
        float ang = (float)pos * inv;
        g_ropetab[n] = make_float2(cosf(ang), sinf(ang));
    }
    if (n == 0) g_uni = 0.f;
}

// ---------------- embed current token ----------------
__global__ void k_embed(const float* __restrict__ in_w, const float* __restrict__ in_b, int step) {
    int idx = blockIdx.x * blockDim.x + threadIdx.x;
    int n = idx >> 8, d = idx & 255;
    g_h[idx] = g_code[n] * in_w[2 * d] + g_xt[n * 4 + step] * in_w[2 * d + 1] + in_b[d];
}

// ---------------- SGEMM: C = A[M,K] @ W[N,K]^T + bias, FFMA2, rope-fused A, split outputs ----
// 128x128 tile, 128 threads, 8x16 micro-tile, double-buffered smem.
__global__ void __launch_bounds__(128) k_gemm(
    const float* __restrict__ A, const float* __restrict__ W,
    const float* __restrict__ bias,
    float* __restrict__ C0, float* __restrict__ C1, float* __restrict__ C2,
    int seg, int N, int K, int relu, int ropeN, const float2* __restrict__ rtab) {
    __shared__ float As[2][16][132];
    __shared__ float Bs[2][16][132];
    const int bm = blockIdx.y * 128;
    const int bn = blockIdx.x * 128;
    const int tid = threadIdx.x;
    const int tx = tid & 7;    // N dir: 8 cols of 16
    const int ty = tid >> 3;   // M dir: 16 rows of 8
    const bool dorope = bn < ropeN;

    unsigned long long acc[8][8];
    #pragma unroll
    for (int m = 0; m < 8; m++)
        #pragma unroll
        for (int p = 0; p < 8; p++) acc[m][p] = 0ull;

    const int nT = K >> 4;
    float4 ra[4], rb[4];

    // prefetch tile 0
    #pragma unroll
    for (int i = 0; i < 4; i++) {
        int idx = tid + i * 128;
        int row = idx >> 2, kq = (idx & 3) << 2;
        ra[i] = *(const float4*)(A + (size_t)(bm + row) * K + kq);
        rb[i] = *(const float4*)(W + (size_t)(bn + row) * K + kq);
    }
    if (dorope) {
        #pragma unroll
        for (int i = 0; i < 4; i++) {
            int idx = tid + i * 128;
            int kq = (idx & 3) << 2;
            int j = kq >> 1;
            float2 cs0 = rtab[j], cs1 = rtab[j + 1];
            float x0 = ra[i].x, y0 = ra[i].y, x1 = ra[i].z, y1 = ra[i].w;
            ra[i].x = x0 * cs0.x - y0 * cs0.y;
            ra[i].y = y0 * cs0.x + x0 * cs0.y;
            ra[i].z = x1 * cs1.x - y1 * cs1.y;
            ra[i].w = y1 * cs1.x + x1 * cs1.y;
        }
    }
    #pragma unroll
    for (int i = 0; i < 4; i++) {
        int idx = tid + i * 128;
        int row = idx >> 2, kq = (idx & 3) << 2;
        As[0][kq + 0][row] = ra[i].x; As[0][kq + 1][row] = ra[i].y;
        As[0][kq + 2][row] = ra[i].z; As[0][kq + 3][row] = ra[i].w;
        Bs[0][kq + 0][row] = rb[i].x; Bs[0][kq + 1][row] = rb[i].y;
        Bs[0][kq + 2][row] = rb[i].z; Bs[0][kq + 3][row] = rb[i].w;
    }
    __syncthreads();

    for (int t = 0; t < nT; t++) {
        const int buf = t & 1;
        if (t + 1 < nT) {
            int k0 = (t + 1) << 4;
            #pragma unroll
            for (int i = 0; i < 4; i++) {
                int idx = tid + i * 128;
                int row = idx >> 2, kq = (idx & 3) << 2;
                ra[i] = *(const float4*)(A + (size_t)(bm + row) * K + k0 + kq);
                rb[i] = *(const float4*)(W + (size_t)(bn + row) * K + k0 + kq);
            }
            if (dorope) {
                #pragma unroll
                for (int i = 0; i < 4; i++) {
                    int idx = tid + i * 128;
                    int kq = (idx & 3) << 2;
                    int j = (k0 + kq) >> 1;
                    float2 cs0 = rtab[j], cs1 = rtab[j + 1];
                    float x0 = ra[i].x, y0 = ra[i].y, x1 = ra[i].z, y1 = ra[i].w;
                    ra[i].x = x0 * cs0.x - y0 * cs0.y;
                    ra[i].y = y0 * cs0.x + x0 * cs0.y;
                    ra[i].z = x1 * cs1.x - y1 * cs1.y;
                    ra[i].w = y1 * cs1.x + x1 * cs1.y;
                }
            }
        }
        #pragma unroll
        for (int kk = 0; kk < 16; kk++) {
            float4 a0 = *(const float4*)&As[buf][kk][ty * 8];
            float4 a1 = *(const float4*)&As[buf][kk][ty * 8 + 4];
            union { float4 v; unsigned long long u[2]; } b4[4];
            b4[0].v = *(const float4*)&Bs[buf][kk][tx * 16];
            b4[1].v = *(const float4*)&Bs[buf][kk][tx * 16 + 4];
            b4[2].v = *(const float4*)&Bs[buf][kk][tx * 16 + 8];
            b4[3].v = *(const float4*)&Bs[buf][kk][tx * 16 + 12];
            unsigned long long ad[8];
            ad[0] = dup2(a0.x); ad[1] = dup2(a0.y); ad[2] = dup2(a0.z); ad[3] = dup2(a0.w);
            ad[4] = dup2(a1.x); ad[5] = dup2(a1.y); ad[6] = dup2(a1.z); ad[7] = dup2(a1.w);
            #pragma unroll
            for (int m = 0; m < 8; m++) {
                #pragma unroll
                for (int q = 0; q < 4; q++) {
                    FMA2(acc[m][2 * q],     ad[m], b4[q].u[0]);
                    FMA2(acc[m][2 * q + 1], ad[m], b4[q].u[1]);
                }
            }
        }
        if (t + 1 < nT) {
            const int nb = (t + 1) & 1;
            #pragma unroll
            for (int i = 0; i < 4; i++) {
                int idx = tid + i * 128;
                int row = idx >> 2, kq = (idx & 3) << 2;
                As[nb][kq + 0][row] = ra[i].x; As[nb][kq + 1][row] = ra[i].y;
                As[nb][kq + 2][row] = ra[i].z; As[nb][kq + 3][row] = ra[i].w;
                Bs[nb][kq + 0][row] = rb[i].x; Bs[nb][kq + 1][row] = rb[i].y;
                Bs[nb][kq + 2][row] = rb[i].z; Bs[nb][kq + 3][row] = rb[i].w;
            }
        }
        __syncthreads();
    }

    // epilogue
    #pragma unroll
    for (int m = 0; m < 8; m++) {
        int row = bm + ty * 8 + m;
        #pragma unroll
        for (int p = 0; p < 8; p++) {
            int col = bn + tx * 16 + 2 * p;
            union { unsigned long long u; float2 f; } v;
            v.u = acc[m][p];
            v.f.x += bias[col];
            v.f.y += bias[col + 1];
            if (relu) { v.f.x = fmaxf(v.f.x, 0.f); v.f.y = fmaxf(v.f.y, 0.f); }
            int s = col / seg;
            float* Cp = (s == 0) ? C0 : ((s == 1) ? C1 : C2);
            *(float2*)(Cp + (size_t)row * seg + (col - s * seg)) = v.f;
        }
    }
}

// ---------------- attention over cached K/V ----------------
__global__ void k_attn(int l, int npos) {
    int n = blockIdx.x;
    int lane = threadIdx.x & 31;
    int col = (threadIdx.x >> 5) * 32 + lane;
    float q = g_qbuf[(size_t)n * DM + col];
    float s[4];
    float m = -1e30f;
    #pragma unroll
    for (int j = 0; j < 4; j++) {
        if (j < npos) {
            float kv = g_kc[((size_t)(l * NSTEP + j) * NR + n) * DM + col];
            float prod = q * kv;
            #pragma unroll
            for (int o = 16; o > 0; o >>= 1) prod += __shfl_xor_sync(0xffffffffu, prod, o);
            s[j] = prod / sqrtf(32.f);
            m = fmaxf(m, s[j]);
        }
    }
    float den = 0.f, o = 0.f;
    #pragma unroll
    for (int j = 0; j < 4; j++) {
        if (j < npos) {
            float p = expf(s[j] - m);
            den += p;
            o += p * g_vc[((size_t)(l * NSTEP + j) * NR + n) * DM + col];
        }
    }
    g_attno[(size_t)n * DM + col] = o / den;
}

// ---------------- residual + layernorm ----------------
__global__ void k_ln(const float* __restrict__ delta, const float* __restrict__ gg,
                     const float* __restrict__ bb) {
    int warp = threadIdx.x >> 5, lane = threadIdx.x & 31;
    int n = blockIdx.x * 8 + warp;
    float v[8];
    float sum = 0.f;
    #pragma unroll
    for (int k = 0; k < 8; k++) {
        int c = k * 32 + lane;
        v[k] = g_h[(size_t)n * DM + c] + delta[(size_t)n * DM + c];
        sum += v[k];
    }
    #pragma unroll
    for (int o = 16; o > 0; o >>= 1) sum += __shfl_xor_sync(0xffffffffu, sum, o);
    float mu = sum / 256.f;
    float var = 0.f;
    #pragma unroll
    for (int k = 0; k < 8; k++) { float d = v[k] - mu; var += d * d; }
    #pragma unroll
    for (int o = 16; o > 0; o >>= 1) var += __shfl_xor_sync(0xffffffffu, var, o);
    var /= 256.f;
    float inv = 1.f / sqrtf(var + 1e-5f);
    #pragma unroll
    for (int k = 0; k < 8; k++) {
        int c = k * 32 + lane;
        g_h[(size_t)n * DM + c] = (v[k] - mu) * inv * gg[c] + bb[c];
    }
}

// ---------------- out projection (N x 9) ----------------
__global__ void k_outproj(const float* __restrict__ out_w, const float* __restrict__ out_b) {
    int warp = threadIdx.x >> 5, lane = threadIdx.x & 31;
    int n = blockIdx.x * 8 + warp;
    float hv[8];
    #pragma unroll
    for (int k = 0; k < 8; k++) hv[k] = g_h[(size_t)n * DM + k * 32 + lane];
    #pragma unroll
    for (int j = 0; j < 9; j++) {
        float acc = 0.f;
        #pragma unroll
        for (int k = 0; k < 8; k++) acc += hv[k] * out_w[j * DM + k * 32 + lane];
        #pragma unroll
        for (int o = 16; o > 0; o >>= 1) acc += __shfl_xor_sync(0xffffffffu, acc, o);
        if (lane == 0) g_z[n * 9 + j] = acc + out_b[j];
    }
}

// ---------------- min/max ----------------
__global__ void k_mm_init() { g_mm[0] = 0xFFFFFFFFu; g_mm[1] = 0u; }

__global__ void k_minmax() {
    __shared__ unsigned smn[256], smx[256];
    int t = threadIdx.x;
    unsigned mn = 0xFFFFFFFFu, mx = 0u;
    for (int n = blockIdx.x * 256 + t; n < NR; n += gridDim.x * 256) {
        unsigned e = f2u(g_z[n * 9]);
        mn = (e < mn) ? e : mn;
        mx = (e > mx) ? e : mx;
    }
    smn[t] = mn; smx[t] = mx;
    __syncthreads();
    for (int s = 128; s > 0; s >>= 1) {
        if (t < s) {
            smn[t] = (smn[t + s] < smn[t]) ? smn[t + s] : smn[t];
            smx[t] = (smx[t + s] > smx[t]) ? smx[t + s] : smx[t];
        }
        __syncthreads();
    }
    if (t == 0) { atomicMin(&g_mm[0], smn[0]); atomicMax(&g_mm[1], smx[0]); }
}

// ---------------- bin assignment ----------------
__global__ void k_bins(int step) {
    int n = blockIdx.x * blockDim.x + threadIdx.x;
    float MN = u2f(g_mm[0]);
    float MX = u2f(g_mm[1]);
    float x = g_z[n * 9];
    float bb[7];
    #pragma unroll
    for (int j = 0; j < 7; j++) bb[j] = g_z[n * 9 + 1 + j];
    int bin = -1;
    float xq = 0.f;
    #pragma unroll
    for (int j = 0; j < 8; j++) {
        float l = (j == 0) ? MN - 0.01f : bb[j - 1];
        float r = (j == 7) ? MX + 0.01f : bb[j];
        if (bin < 0 && x >= l && x < r && r > l) { bin = j; xq = (l + r) * 0.5f; }
    }
    g_bin[n] = bin;
    g_zarr[step * NR + n] = x;
    g_qarr[step * NR + n] = xq;
}

// ---------------- histogram ----------------
__global__ void k_histzero() {
    int i = blockIdx.x * blockDim.x + threadIdx.x;
    if (i < VOC * KL) g_Hc[i] = 0.f;
    else if (i < VOC * KL + VOC) g_Hm1[i - VOC * KL] = 0.f;
}

__global__ void k_hist() {
    int n = blockIdx.x * 256 + threadIdx.x;
    int g = g_gid[n];
    if (g < 0 || g >= VOC) return;
    int bin = g_bin[n];
    if (bin >= 0) atomicAdd(&g_Hc[g * KL + bin], 1.f);
    else atomicAdd(&g_Hm1[g], 1.f);
}

// ---------------- ratios update ----------------
__global__ void k_ratupd() {
    int v = blockIdx.x * 256 + threadIdx.x;
    #pragma unroll
    for (int k = 0; k < 7; k++) {
        float hc = g_Hc[v * KL + k];
        if (hc > 0.f) g_rat[v * KL + k] = hc;
    }
    float hc7 = g_Hc[v * KL + 7], hm = g_Hm1[v], old7 = g_rat[v * KL + 7];
    g_rat[v * KL + 7] = hc7 > 0.f ? hc7 : (hm > 0.f ? hm : old7);
}

// ---------------- grad dot + order clip ----------------
__global__ void __launch_bounds__(256) k_grad(int step) {
    __shared__ float sd[256], sc[256];
    int t = threadIdx.x;
    int n = blockIdx.x * 256 + t;
    int g = g_gid[n];
    g = g < 0 ? 0 : (g > VOC - 1 ? VOC - 1 : g);
    float r[8];
    #pragma unroll
    for (int k = 0; k < 8; k++) r[k] = g_rat[g * KL + k];
    float gr[7];
    float nrm = 0.f;
    #pragma unroll
    for (int k = 0; k < 7; k++) { gr[k] = -(r[k + 1] - r[k]); nrm += gr[k] * gr[k]; }
    nrm = sqrtf(nrm);
    float bby[7];
    #pragma unroll
    for (int k = 0; k < 7; k++) bby[k] = g_z[n * 9 + 1 + k];
    float dot = 0.f;
    #pragma unroll
    for (int k = 0; k < 7; k++) dot += bby[k] * (gr[k] / nrm);
    float cl = 0.f;
    #pragma unroll
    for (int k = 0; k < 6; k++) {
        float d = bby[k + 1] - bby[k];
        d = fmaxf(d, -9999999.f);
        d = fminf(d, 0.1f);
        cl += d;
    }
    int bin = g_bin[n];
    g_gid[n] += bin * (1 << (3 * step));
    g_code[n] = (float)bin;
    sd[t] = dot; sc[t] = cl;
    __syncthreads();
    for (int s = 128; s > 0; s >>= 1) {
        if (t < s) { sd[t] += sd[t + s]; sc[t] += sc[t + s]; }
        __syncthreads();
    }
    if (t == 0) { g_pdot[blockIdx.x] = sd[0]; g_pclip[blockIdx.x] = sc[0]; }
}

__global__ void k_losses() {
    __shared__ float sd[128], sc[128];
    int t = threadIdx.x;
    sd[t] = g_pdot[t]; sc[t] = g_pclip[t];
    __syncthreads();
    for (int s = 64; s > 0; s >>= 1) {
        if (t < s) { sd[t] += sd[t + s]; sc[t] += sc[t + s]; }
        __syncthreads();
    }
    if (t == 0) g_uni += sd[0] / (float)NR - sc[0] / ((float)NR * 6.f);
}

// ---------------- vq loss partials ----------------
__global__ void k_vqpart() {
    __shared__ float s[256];
    int t = threadIdx.x;
    int n = blockIdx.x * 256 + t;
    float acc = 0.f;
    #pragma unroll
    for (int j = 0; j < NSTEP; j++) {
        float d = g_qarr[j * NR + n] - g_zarr[j * NR + n];
        acc += d * d;
    }
    s[t] = acc;
    __syncthreads();
    for (int r = 128; r > 0; r >>= 1) {
        if (t < r) s[t] += s[t + r];
        __syncthreads();
    }
    if (t == 0) g_pvq[blockIdx.x] = s[0];
}

// ---------------- final projection ----------------
__global__ void k_zq(const float* __restrict__ ppw, const float* __restrict__ ppb,
                     float* __restrict__ out) {
    int t = blockIdx.x * blockDim.x + threadIdx.x;
    int b = t >> 15;
    int rem = t & 32767;
    int cz = rem >> 10;
    int l = rem & 1023;
    int n = (b << 10) + l;
    float acc = ppb[cz];
    #pragma unroll
    for (int j = 0; j < 4; j++) {
        float q = g_qarr[j * NR + n], z = g_zarr[j * NR + n];
        float s = (q + z) - z;
        acc += s * ppw[cz * 4 + j];
    }
    out[t] = acc;
}

__global__ void k_scalars(float* __restrict__ out, int out_size) {
    __shared__ float s[128];
    int t = threadIdx.x;
    s[t] = g_pvq[t];
    __syncthreads();
    for (int r = 64; r > 0; r >>= 1) {
        if (t < r) s[t] += s[t + r];
        __syncthreads();
    }
    if (t == 0) {
        out[out_size - 2] = s[0] / (float)(NR * NSTEP);
        out[out_size - 1] = g_uni;
    }
}

// ---------------- host ----------------
static void gemm(const float* A, const float* W, const float* bias,
                 float* C0, float* C1, float* C2, int seg,
                 int N, int K, int relu, int ropeN, const float2* rtab) {
    dim3 grid(N / 128, NR / 128);
    k_gemm<<<grid, 128>>>(A, W, bias, C0, C1, C2, seg, N, K, relu, ropeN, rtab);
}

extern "C" void kernel_launch(void* const* d_in, const int* in_sizes, int n_in,
                              void* d_out, int out_size) {
    const float* x     = (const float*)d_in[0];
    const float* ppvw  = (const float*)d_in[1];
    const float* ppvb  = (const float*)d_in[2];
    const float* ppow  = (const float*)d_in[3];
    const float* ppob  = (const float*)d_in[4];
    const float* in_w  = (const float*)d_in[5];
    const float* in_b  = (const float*)d_in[6];
    const float* out_w = (const float*)d_in[7];
    const float* out_b = (const float*)d_in[8];
    const float* qkv_w = (const float*)d_in[9];
    const float* qkv_b = (const float*)d_in[10];
    const float* ao_w  = (const float*)d_in[11];
    const float* ao_b  = (const float*)d_in[12];
    const float* f1_w  = (const float*)d_in[13];
    const float* f1_b  = (const float*)d_in[14];
    const float* f2_w  = (const float*)d_in[15];
    const float* f2_b  = (const float*)d_in[16];
    const float* ln1g  = (const float*)d_in[17];
    const float* ln1b  = (const float*)d_in[18];
    const float* ln2g  = (const float*)d_in[19];
    const float* ln2b  = (const float*)d_in[20];
    const float* rat0  = (const float*)d_in[21];
    float* out = (float*)d_out;

    float *h, *qb, *at_o, *d1, *d2, *kc, *vc;
    float2* rtab;
    cudaGetSymbolAddress((void**)&h,    g_h);
    cudaGetSymbolAddress((void**)&qb,   g_qbuf);
    cudaGetSymbolAddress((void**)&at_o, g_attno);
    cudaGetSymbolAddress((void**)&d1,   g_d1);
    cudaGetSymbolAddress((void**)&d2,   g_d2);
    cudaGetSymbolAddress((void**)&kc,   g_kc);
    cudaGetSymbolAddress((void**)&vc,   g_vc);
    cudaGetSymbolAddress((void**)&rtab, g_ropetab);

    k_init<<<NR / 256, 256>>>(x, ppvw, ppvb, rat0);

    for (int i = 0; i < NSTEP; i++) {
        k_embed<<<NR * DM / 256, 256>>>(in_w, in_b, i);
        for (int l = 0; l < NLAY; l++) {
            const float* Wl = qkv_w + (size_t)l * 768 * DM;
            const float* bl = qkv_b + l * 768;
            float* kslot = kc + (size_t)(l * NSTEP + i) * NR * DM;
            float* vslot = vc + (size_t)(l * NSTEP + i) * NR * DM;
            // fused QKV: N=768, rope applied to A for cols [0,512), split outputs
            gemm(h, Wl, bl, qb, kslot, vslot, 256, 768, DM, 0, 512, rtab + i * 128);
            k_attn<<<NR, 256>>>(l, i + 1);
            gemm(at_o, ao_w + (size_t)l * DM * DM, ao_b + l * DM,
                 d1, nullptr, nullptr, DM, DM, DM, 0, 0, rtab);
            k_ln<<<NR / 8, 256>>>(d1, ln1g + l * DM, ln1b + l * DM);
            gemm(h, f1_w + (size_t)l * FFD * DM, f1_b + l * FFD,
                 d2, nullptr, nullptr, FFD, FFD, DM, 1, 0, rtab);
            gemm(d2, f2_w + (size_t)l * DM * FFD, f2_b + l * DM,
                 d1, nullptr, nullptr, DM, DM, FFD, 0, 0, rtab);
            k_ln<<<NR / 8, 256>>>(d1, ln2g + l * DM, ln2b + l * DM);
        }
        k_outproj<<<NR / 8, 256>>>(out_w, out_b);
        k_mm_init<<<1, 1>>>();
        k_minmax<<<64, 256>>>();
        k_bins<<<NR / 256, 256>>>(i);
        k_histzero<<<(VOC * KL + VOC + 255) / 256, 256>>>();
        k_hist<<<NR / 256, 256>>>();
        k_ratupd<<<VOC / 256, 256>>>();
        k_grad<<<128, 256>>>(i);
        k_losses<<<1, 128>>>();
    }

    k_vqpart<<<128, 256>>>();
    k_zq<<<(NR * 32) / 256, 256>>>(ppow, ppob, out);
    k_scalars<<<1, 128>>>(out, out_size);
}

// round 3
// speedup vs baseline: 1.5693x; 1.5693x over previous
#include <cuda_runtime.h>
#include <math.h>

#define NR 32768
#define DM 256
#define NLAY 3
#define NSTEP 4
#define FFD 512
#define VOC 4096
#define KL 8

// ---------------- persistent device scratch ----------------
__device__ float g_xt[NR * 4];
__device__ float g_code[NR];
__device__ int   g_gid[NR];
__device__ int   g_bin[NR];
__device__ float g_h[NR * DM];
__device__ float g_qbuf[NR * DM];
__device__ float g_attno[NR * DM];
__device__ float g_d1[NR * DM];
__device__ float g_d2[NR * FFD];
__device__ float g_kc[NLAY * NSTEP * NR * DM];
__device__ float g_vc[NLAY * NSTEP * NR * DM];
__device__ float g_z[NR * 9];
__device__ float g_zarr[NSTEP * NR];
__device__ float g_qarr[NSTEP * NR];
__device__ float g_Hc[VOC * KL];
__device__ float g_Hm1[VOC];
__device__ float g_rat[VOC * KL];
__device__ float2 g_ropetab[NSTEP * 128];
__device__ unsigned g_mm[2];
__device__ float g_pdot[128];
__device__ float g_pclip[128];
__device__ float g_pvq[128];
__device__ float g_uni;

// ---------------- helpers ----------------
__device__ __forceinline__ unsigned f2u(float f) {
    unsigned u = __float_as_uint(f);
    return (u & 0x80000000u) ? ~u : (u | 0x80000000u);
}
__device__ __forceinline__ float u2f(unsigned u) {
    u = (u & 0x80000000u) ? (u & 0x7fffffffu) : ~u;
    return __uint_as_float(u);
}

#define FMA2(d, a, b) asm("fma.rn.f32x2 %0, %1, %2, %0;" : "+l"(d) : "l"(a), "l"(b))
__device__ __forceinline__ unsigned long long dup2(float x) {
    unsigned long long r;
    asm("mov.b64 %0, {%1, %1};" : "=l"(r) : "r"(__float_as_uint(x)));
    return r;
}

// ---------------- init ----------------
__global__ void k_init(const float* __restrict__ x, const float* __restrict__ pw,
                       const float* __restrict__ pb, const float* __restrict__ rat0) {
    int n = blockIdx.x * blockDim.x + threadIdx.x;
    if (n < NR) {
        int b = n >> 10, l = n & 1023;
        const float* xb = x + (size_t)b * 32768 + l;
        #pragma unroll
        for (int j = 0; j < 4; j++) {
            float acc = pb[j];
            #pragma unroll
            for (int cz = 0; cz < 32; cz++) acc += xb[cz * 1024] * pw[j * 32 + cz];
            g_xt[n * 4 + j] = tanhf(acc);
        }
        g_code[n] = 0.f;
        g_gid[n] = 0;
    }
    if (n < VOC * KL) g_rat[n] = rat0[n];
    if (n < NSTEP * 128) {
        int pos = n >> 7, j = n & 127;
        float inv = powf(10000.f, -(float)(2 * j) / 256.f);
        float ang = (float)pos * inv;
        g_ropetab[n] = make_float2(cosf(ang), sinf(ang));
    }
    if (n == 0) g_uni = 0.f;
}

// ---------------- embed current token ----------------
__global__ void k_embed(const float* __restrict__ in_w, const float* __restrict__ in_b, int step) {
    int idx = blockIdx.x * blockDim.x + threadIdx.x;
    int n = idx >> 8, d = idx & 255;
    g_h[idx] = g_code[n] * in_w[2 * d] + g_xt[n * 4 + step] * in_w[2 * d + 1] + in_b[d];
}

// ---------------- SGEMM: C = A[M,K] @ W[N,K]^T + bias ----------------
// 128x128 tile, 256 threads, 8x8 micro-tile (FFMA2), double-buffered smem,
// rope fused on A loads, up to 3-way column-split outputs.
__global__ void __launch_bounds__(256, 2) k_gemm(
    const float* __restrict__ A, const float* __restrict__ W,
    const float* __restrict__ bias,
    float* __restrict__ C0, float* __restrict__ C1, float* __restrict__ C2,
    int seg, int N, int K, int relu, int ropeN, const float2* __restrict__ rtab) {
    __shared__ float As[2][16][132];
    __shared__ float Bs[2][16][132];
    const int bm = blockIdx.y * 128;
    const int bn = blockIdx.x * 128;
    const int tid = threadIdx.x;
    const int tx = tid & 15;   // N dir: 16 threads x (4+4 split cols)
    const int ty = tid >> 4;   // M dir: 16 threads x 8 rows
    const bool dorope = bn < ropeN;

    unsigned long long acc[8][4];
    #pragma unroll
    for (int m = 0; m < 8; m++)
        #pragma unroll
        for (int p = 0; p < 4; p++) acc[m][p] = 0ull;

    const int nT = K >> 4;
    float4 ra[2], rb[2];

    // prefetch tile 0
    #pragma unroll
    for (int i = 0; i < 2; i++) {
        int idx = tid + i * 256;
        int row = idx >> 2, kq = (idx & 3) << 2;
        ra[i] = *(const float4*)(A + (size_t)(bm + row) * K + kq);
        rb[i] = *(const float4*)(W + (size_t)(bn + row) * K + kq);
    }
    if (dorope) {
        #pragma unroll
        for (int i = 0; i < 2; i++) {
            int idx = tid + i * 256;
            int kq = (idx & 3) << 2;
            int j = kq >> 1;
            float2 cs0 = rtab[j], cs1 = rtab[j + 1];
            float x0 = ra[i].x, y0 = ra[i].y, x1 = ra[i].z, y1 = ra[i].w;
            ra[i].x = x0 * cs0.x - y0 * cs0.y;
            ra[i].y = y0 * cs0.x + x0 * cs0.y;
            ra[i].z = x1 * cs1.x - y1 * cs1.y;
            ra[i].w = y1 * cs1.x + x1 * cs1.y;
        }
    }
    #pragma unroll
    for (int i = 0; i < 2; i++) {
        int idx = tid + i * 256;
        int row = idx >> 2, kq = (idx & 3) << 2;
        As[0][kq + 0][row] = ra[i].x; As[0][kq + 1][row] = ra[i].y;
        As[0][kq + 2][row] = ra[i].z; As[0][kq + 3][row] = ra[i].w;
        Bs[0][kq + 0][row] = rb[i].x; Bs[0][kq + 1][row] = rb[i].y;
        Bs[0][kq + 2][row] = rb[i].z; Bs[0][kq + 3][row] = rb[i].w;
    }
    __syncthreads();

    for (int t = 0; t < nT; t++) {
        const int buf = t & 1;
        if (t + 1 < nT) {
            int k0 = (t + 1) << 4;
            #pragma unroll
            for (int i = 0; i < 2; i++) {
                int idx = tid + i * 256;
                int row = idx >> 2, kq = (idx & 3) << 2;
                ra[i] = *(const float4*)(A + (size_t)(bm + row) * K + k0 + kq);
                rb[i] = *(const float4*)(W + (size_t)(bn + row) * K + k0 + kq);
            }
            if (dorope) {
                #pragma unroll
                for (int i = 0; i < 2; i++) {
                    int idx = tid + i * 256;
                    int kq = (idx & 3) << 2;
                    int j = (k0 + kq) >> 1;
                    float2 cs0 = rtab[j], cs1 = rtab[j + 1];
                    float x0 = ra[i].x, y0 = ra[i].y, x1 = ra[i].z, y1 = ra[i].w;
                    ra[i].x = x0 * cs0.x - y0 * cs0.y;
                    ra[i].y = y0 * cs0.x + x0 * cs0.y;
                    ra[i].z = x1 * cs1.x - y1 * cs1.y;
                    ra[i].w = y1 * cs1.x + x1 * cs1.y;
                }
            }
        }
        #pragma unroll
        for (int kk = 0; kk < 16; kk++) {
            float4 a0 = *(const float4*)&As[buf][kk][ty * 8];
            float4 a1 = *(const float4*)&As[buf][kk][ty * 8 + 4];
            union { float4 v; unsigned long long u[2]; } b0, b1;
            b0.v = *(const float4*)&Bs[buf][kk][tx * 4];
            b1.v = *(const float4*)&Bs[buf][kk][64 + tx * 4];
            unsigned long long ad[8];
            ad[0] = dup2(a0.x); ad[1] = dup2(a0.y); ad[2] = dup2(a0.z); ad[3] = dup2(a0.w);
            ad[4] = dup2(a1.x); ad[5] = dup2(a1.y); ad[6] = dup2(a1.z); ad[7] = dup2(a1.w);
            #pragma unroll
            for (int m = 0; m < 8; m++) {
                FMA2(acc[m][0], ad[m], b0.u[0]);
                FMA2(acc[m][1], ad[m], b0.u[1]);
                FMA2(acc[m][2], ad[m], b1.u[0]);
                FMA2(acc[m][3], ad[m], b1.u[1]);
            }
        }
        if (t + 1 < nT) {
            const int nb = (t + 1) & 1;
            #pragma unroll
            for (int i = 0; i < 2; i++) {
                int idx = tid + i * 256;
                int row = idx >> 2, kq = (idx & 3) << 2;
                As[nb][kq + 0][row] = ra[i].x; As[nb][kq + 1][row] = ra[i].y;
                As[nb][kq + 2][row] = ra[i].z; As[nb][kq + 3][row] = ra[i].w;
                Bs[nb][kq + 0][row] = rb[i].x; Bs[nb][kq + 1][row] = rb[i].y;
                Bs[nb][kq + 2][row] = rb[i].z; Bs[nb][kq + 3][row] = rb[i].w;
            }
        }
        __syncthreads();
    }

    // epilogue: cols tx*4 + half*64
    #pragma unroll
    for (int m = 0; m < 8; m++) {
        int row = bm + ty * 8 + m;
        #pragma unroll
        for (int p = 0; p < 4; p++) {
            int half = p >> 1;
            int col = bn + half * 64 + tx * 4 + (p & 1) * 2;
            union { unsigned long long u; float2 f; } v;
            v.u = acc[m][p];
            v.f.x += bias[col];
            v.f.y += bias[col + 1];
            if (relu) { v.f.x = fmaxf(v.f.x, 0.f); v.f.y = fmaxf(v.f.y, 0.f); }
            int s = col / seg;
            float* Cp = (s == 0) ? C0 : ((s == 1) ? C1 : C2);
            *(float2*)(Cp + (size_t)row * seg + (col - s * seg)) = v.f;
        }
    }
}

// ---------------- attention over cached K/V ----------------
__global__ void k_attn(int l, int npos) {
    int n = blockIdx.x;
    int lane = threadIdx.x & 31;
    int col = (threadIdx.x >> 5) * 32 + lane;
    float q = g_qbuf[(size_t)n * DM + col];
    float s[4];
    float m = -1e30f;
    #pragma unroll
    for (int j = 0; j < 4; j++) {
        if (j < npos) {
            float kv = g_kc[((size_t)(l * NSTEP + j) * NR + n) * DM + col];
            float prod = q * kv;
            #pragma unroll
            for (int o = 16; o > 0; o >>= 1) prod += __shfl_xor_sync(0xffffffffu, prod, o);
            s[j] = prod / sqrtf(32.f);
            m = fmaxf(m, s[j]);
        }
    }
    float den = 0.f, o = 0.f;
    #pragma unroll
    for (int j = 0; j < 4; j++) {
        if (j < npos) {
            float p = expf(s[j] - m);
            den += p;
            o += p * g_vc[((size_t)(l * NSTEP + j) * NR + n) * DM + col];
        }
    }
    g_attno[(size_t)n * DM + col] = o / den;
}

// ---------------- residual + layernorm ----------------
__global__ void k_ln(const float* __restrict__ delta, const float* __restrict__ gg,
                     const float* __restrict__ bb) {
    int warp = threadIdx.x >> 5, lane = threadIdx.x & 31;
    int n = blockIdx.x * 8 + warp;
    float v[8];
    float sum = 0.f;
    #pragma unroll
    for (int k = 0; k < 8; k++) {
        int c = k * 32 + lane;
        v[k] = g_h[(size_t)n * DM + c] + delta[(size_t)n * DM + c];
        sum += v[k];
    }
    #pragma unroll
    for (int o = 16; o > 0; o >>= 1) sum += __shfl_xor_sync(0xffffffffu, sum, o);
    float mu = sum / 256.f;
    float var = 0.f;
    #pragma unroll
    for (int k = 0; k < 8; k++) { float d = v[k] - mu; var += d * d; }
    #pragma unroll
    for (int o = 16; o > 0; o >>= 1) var += __shfl_xor_sync(0xffffffffu, var, o);
    var /= 256.f;
    float inv = 1.f / sqrtf(var + 1e-5f);
    #pragma unroll
    for (int k = 0; k < 8; k++) {
        int c = k * 32 + lane;
        g_h[(size_t)n * DM + c] = (v[k] - mu) * inv * gg[c] + bb[c];
    }
}

// ---------------- out projection (N x 9) ----------------
__global__ void k_outproj(const float* __restrict__ out_w, const float* __restrict__ out_b) {
    int warp = threadIdx.x >> 5, lane = threadIdx.x & 31;
    int n = blockIdx.x * 8 + warp;
    float hv[8];
    #pragma unroll
    for (int k = 0; k < 8; k++) hv[k] = g_h[(size_t)n * DM + k * 32 + lane];
    #pragma unroll
    for (int j = 0; j < 9; j++) {
        float acc = 0.f;
        #pragma unroll
        for (int k = 0; k < 8; k++) acc += hv[k] * out_w[j * DM + k * 32 + lane];
        #pragma unroll
        for (int o = 16; o > 0; o >>= 1) acc += __shfl_xor_sync(0xffffffffu, acc, o);
        if (lane == 0) g_z[n * 9 + j] = acc + out_b[j];
    }
}

// ---------------- min/max ----------------
__global__ void k_mm_init() { g_mm[0] = 0xFFFFFFFFu; g_mm[1] = 0u; }

__global__ void k_minmax() {
    __shared__ unsigned smn[256], smx[256];
    int t = threadIdx.x;
    unsigned mn = 0xFFFFFFFFu, mx = 0u;
    for (int n = blockIdx.x * 256 + t; n < NR; n += gridDim.x * 256) {
        unsigned e = f2u(g_z[n * 9]);
        mn = (e < mn) ? e : mn;
        mx = (e > mx) ? e : mx;
    }
    smn[t] = mn; smx[t] = mx;
    __syncthreads();
    for (int s = 128; s > 0; s >>= 1) {
        if (t < s) {
            smn[t] = (smn[t + s] < smn[t]) ? smn[t + s] : smn[t];
            smx[t] = (smx[t + s] > smx[t]) ? smx[t + s] : smx[t];
        }
        __syncthreads();
    }
    if (t == 0) { atomicMin(&g_mm[0], smn[0]); atomicMax(&g_mm[1], smx[0]); }
}

// ---------------- bin assignment ----------------
__global__ void k_bins(int step) {
    int n = blockIdx.x * blockDim.x + threadIdx.x;
    float MN = u2f(g_mm[0]);
    float MX = u2f(g_mm[1]);
    float x = g_z[n * 9];
    float bb[7];
    #pragma unroll
    for (int j = 0; j < 7; j++) bb[j] = g_z[n * 9 + 1 + j];
    int bin = -1;
    float xq = 0.f;
    #pragma unroll
    for (int j = 0; j < 8; j++) {
        float l = (j == 0) ? MN - 0.01f : bb[j - 1];
        float r = (j == 7) ? MX + 0.01f : bb[j];
        if (bin < 0 && x >= l && x < r && r > l) { bin = j; xq = (l + r) * 0.5f; }
    }
    g_bin[n] = bin;
    g_zarr[step * NR + n] = x;
    g_qarr[step * NR + n] = xq;
}

// ---------------- histogram ----------------
__global__ void k_histzero() {
    int i = blockIdx.x * blockDim.x + threadIdx.x;
    if (i < VOC * KL) g_Hc[i] = 0.f;
    else if (i < VOC * KL + VOC) g_Hm1[i - VOC * KL] = 0.f;
}

__global__ void k_hist() {
    int n = blockIdx.x * 256 + threadIdx.x;
    int g = g_gid[n];
    if (g < 0 || g >= VOC) return;
    int bin = g_bin[n];
    if (bin >= 0) atomicAdd(&g_Hc[g * KL + bin], 1.f);
    else atomicAdd(&g_Hm1[g], 1.f);
}

// ---------------- ratios update ----------------
__global__ void k_ratupd() {
    int v = blockIdx.x * 256 + threadIdx.x;
    #pragma unroll
    for (int k = 0; k < 7; k++) {
        float hc = g_Hc[v * KL + k];
        if (hc > 0.f) g_rat[v * KL + k] = hc;
    }
    float hc7 = g_Hc[v * KL + 7], hm = g_Hm1[v], old7 = g_rat[v * KL + 7];
    g_rat[v * KL + 7] = hc7 > 0.f ? hc7 : (hm > 0.f ? hm : old7);
}

// ---------------- grad dot + order clip ----------------
__global__ void __launch_bounds__(256) k_grad(int step) {
    __shared__ float sd[256], sc[256];
    int t = threadIdx.x;
    int n = blockIdx.x * 256 + t;
    int g = g_gid[n];
    g = g < 0 ? 0 : (g > VOC - 1 ? VOC - 1 : g);
    float r[8];
    #pragma unroll
    for (int k = 0; k < 8; k++) r[k] = g_rat[g * KL + k];
    float gr[7];
    float nrm = 0.f;
    #pragma unroll
    for (int k = 0; k < 7; k++) { gr[k] = -(r[k + 1] - r[k]); nrm += gr[k] * gr[k]; }
    nrm = sqrtf(nrm);
    float bby[7];
    #pragma unroll
    for (int k = 0; k < 7; k++) bby[k] = g_z[n * 9 + 1 + k];
    float dot = 0.f;
    #pragma unroll
    for (int k = 0; k < 7; k++) dot += bby[k] * (gr[k] / nrm);
    float cl = 0.f;
    #pragma unroll
    for (int k = 0; k < 6; k++) {
        float d = bby[k + 1] - bby[k];
        d = fmaxf(d, -9999999.f);
        d = fminf(d, 0.1f);
        cl += d;
    }
    int bin = g_bin[n];
    g_gid[n] += bin * (1 << (3 * step));
    g_code[n] = (float)bin;
    sd[t] = dot; sc[t] = cl;
    __syncthreads();
    for (int s = 128; s > 0; s >>= 1) {
        if (t < s) { sd[t] += sd[t + s]; sc[t] += sc[t + s]; }
        __syncthreads();
    }
    if (t == 0) { g_pdot[blockIdx.x] = sd[0]; g_pclip[blockIdx.x] = sc[0]; }
}

__global__ void k_losses() {
    __shared__ float sd[128], sc[128];
    int t = threadIdx.x;
    sd[t] = g_pdot[t]; sc[t] = g_pclip[t];
    __syncthreads();
    for (int s = 64; s > 0; s >>= 1) {
        if (t < s) { sd[t] += sd[t + s]; sc[t] += sc[t + s]; }
        __syncthreads();
    }
    if (t == 0) g_uni += sd[0] / (float)NR - sc[0] / ((float)NR * 6.f);
}

// ---------------- vq loss partials ----------------
__global__ void k_vqpart() {
    __shared__ float s[256];
    int t = threadIdx.x;
    int n = blockIdx.x * 256 + t;
    float acc = 0.f;
    #pragma unroll
    for (int j = 0; j < NSTEP; j++) {
        float d = g_qarr[j * NR + n] - g_zarr[j * NR + n];
        acc += d * d;
    }
    s[t] = acc;
    __syncthreads();
    for (int r = 128; r > 0; r >>= 1) {
        if (t < r) s[t] += s[t + r];
        __syncthreads();
    }
    if (t == 0) g_pvq[blockIdx.x] = s[0];
}

// ---------------- final projection ----------------
__global__ void k_zq(const float* __restrict__ ppw, const float* __restrict__ ppb,
                     float* __restrict__ out) {
    int t = blockIdx.x * blockDim.x + threadIdx.x;
    int b = t >> 15;
    int rem = t & 32767;
    int cz = rem >> 10;
    int l = rem & 1023;
    int n = (b << 10) + l;
    float acc = ppb[cz];
    #pragma unroll
    for (int j = 0; j < 4; j++) {
        float q = g_qarr[j * NR + n], z = g_zarr[j * NR + n];
        float s = (q + z) - z;
        acc += s * ppw[cz * 4 + j];
    }
    out[t] = acc;
}

__global__ void k_scalars(float* __restrict__ out, int out_size) {
    __shared__ float s[128];
    int t = threadIdx.x;
    s[t] = g_pvq[t];
    __syncthreads();
    for (int r = 64; r > 0; r >>= 1) {
        if (t < r) s[t] += s[t + r];
        __syncthreads();
    }
    if (t == 0) {
        out[out_size - 2] = s[0] / (float)(NR * NSTEP);
        out[out_size - 1] = g_uni;
    }
}

// ---------------- host ----------------
static void gemm(const float* A, const float* W, const float* bias,
                 float* C0, float* C1, float* C2, int seg,
                 int N, int K, int relu, int ropeN, const float2* rtab) {
    dim3 grid(N / 128, NR / 128);
    k_gemm<<<grid, 256>>>(A, W, bias, C0, C1, C2, seg, N, K, relu, ropeN, rtab);
}

extern "C" void kernel_launch(void* const* d_in, const int* in_sizes, int n_in,
                              void* d_out, int out_size) {
    const float* x     = (const float*)d_in[0];
    const float* ppvw  = (const float*)d_in[1];
    const float* ppvb  = (const float*)d_in[2];
    const float* ppow  = (const float*)d_in[3];
    const float* ppob  = (const float*)d_in[4];
    const float* in_w  = (const float*)d_in[5];
    const float* in_b  = (const float*)d_in[6];
    const float* out_w = (const float*)d_in[7];
    const float* out_b = (const float*)d_in[8];
    const float* qkv_w = (const float*)d_in[9];
    const float* qkv_b = (const float*)d_in[10];
    const float* ao_w  = (const float*)d_in[11];
    const float* ao_b  = (const float*)d_in[12];
    const float* f1_w  = (const float*)d_in[13];
    const float* f1_b  = (const float*)d_in[14];
    const float* f2_w  = (const float*)d_in[15];
    const float* f2_b  = (const float*)d_in[16];
    const float* ln1g  = (const float*)d_in[17];
    const float* ln1b  = (const float*)d_in[18];
    const float* ln2g  = (const float*)d_in[19];
    const float* ln2b  = (const float*)d_in[20];
    const float* rat0  = (const float*)d_in[21];
    float* out = (float*)d_out;

    float *h, *qb, *at_o, *d1, *d2, *kc, *vc;
    float2* rtab;
    cudaGetSymbolAddress((void**)&h,    g_h);
    cudaGetSymbolAddress((void**)&qb,   g_qbuf);
    cudaGetSymbolAddress((void**)&at_o, g_attno);
    cudaGetSymbolAddress((void**)&d1,   g_d1);
    cudaGetSymbolAddress((void**)&d2,   g_d2);
    cudaGetSymbolAddress((void**)&kc,   g_kc);
    cudaGetSymbolAddress((void**)&vc,   g_vc);
    cudaGetSymbolAddress((void**)&rtab, g_ropetab);

    k_init<<<NR / 256, 256>>>(x, ppvw, ppvb, rat0);

    for (int i = 0; i < NSTEP; i++) {
        k_embed<<<NR * DM / 256, 256>>>(in_w, in_b, i);
        for (int l = 0; l < NLAY; l++) {
            const float* Wl = qkv_w + (size_t)l * 768 * DM;
            const float* bl = qkv_b + l * 768;
            float* kslot = kc + (size_t)(l * NSTEP + i) * NR * DM;
            float* vslot = vc + (size_t)(l * NSTEP + i) * NR * DM;
            // fused QKV: N=768, rope on A for cols [0,512), split outputs
            gemm(h, Wl, bl, qb, kslot, vslot, 256, 768, DM, 0, 512, rtab + i * 128);
            k_attn<<<NR, 256>>>(l, i + 1);
            gemm(at_o, ao_w + (size_t)l * DM * DM, ao_b + l * DM,
                 d1, nullptr, nullptr, DM, DM, DM, 0, 0, rtab);
            k_ln<<<NR / 8, 256>>>(d1, ln1g + l * DM, ln1b + l * DM);
            gemm(h, f1_w + (size_t)l * FFD * DM, f1_b + l * FFD,
                 d2, nullptr, nullptr, FFD, FFD, DM, 1, 0, rtab);
            gemm(d2, f2_w + (size_t)l * DM * FFD, f2_b + l * DM,
                 d1, nullptr, nullptr, DM, DM, FFD, 0, 0, rtab);
            k_ln<<<NR / 8, 256>>>(d1, ln2g + l * DM, ln2b + l * DM);
        }
        k_outproj<<<NR / 8, 256>>>(out_w, out_b);
        k_mm_init<<<1, 1>>>();
        k_minmax<<<64, 256>>>();
        k_bins<<<NR / 256, 256>>>(i);
        k_histzero<<<(VOC * KL + VOC + 255) / 256, 256>>>();
        k_hist<<<NR / 256, 256>>>();
        k_ratupd<<<VOC / 256, 256>>>();
        k_grad<<<128, 256>>>(i);
        k_losses<<<1, 128>>>();
    }

    k_vqpart<<<128, 256>>>();
    k_zq<<<(NR * 32) / 256, 256>>>(ppow, ppob, out);
    k_scalars<<<1, 128>>>(out, out_size);
}

// round 4
// speedup vs baseline: 1.6637x; 1.0601x over previous
#include <cuda_runtime.h>
#include <math.h>

#define NR 32768
#define DM 256
#define NLAY 3
#define NSTEP 4
#define FFD 512
#define VOC 4096
#define KL 8

// ---------------- persistent device scratch ----------------
__device__ float g_xt[NR * 4];
__device__ float g_code[NR];
__device__ int   g_gid[NR];
__device__ int   g_bin[NR];
__device__ float g_h[NR * DM];
__device__ float g_qbuf[NR * DM];
__device__ float g_attno[NR * DM];
__device__ float g_d1[NR * DM];
__device__ float g_d2[NR * FFD];
__device__ float g_kc[NLAY * NSTEP * NR * DM];
__device__ float g_vc[NLAY * NSTEP * NR * DM];
__device__ float g_z[NR * 9];
__device__ float g_zarr[NSTEP * NR];
__device__ float g_qarr[NSTEP * NR];
__device__ float g_Hc[VOC * KL];
__device__ float g_Hm1[VOC];
__device__ float g_rat[VOC * KL];
__device__ float2 g_ropetab[NSTEP * 128];
__device__ unsigned g_mm[2];
__device__ float g_pdot[128];
__device__ float g_pclip[128];
__device__ float g_pvq[128];
__device__ float g_uni;

// ---------------- helpers ----------------
__device__ __forceinline__ unsigned f2u(float f) {
    unsigned u = __float_as_uint(f);
    return (u & 0x80000000u) ? ~u : (u | 0x80000000u);
}
__device__ __forceinline__ float u2f(unsigned u) {
    u = (u & 0x80000000u) ? (u & 0x7fffffffu) : ~u;
    return __uint_as_float(u);
}

#define FMA2(d, a, b) asm("fma.rn.f32x2 %0, %1, %2, %0;" : "+l"(d) : "l"(a), "l"(b))
__device__ __forceinline__ unsigned long long dup2(float x) {
    unsigned long long r;
    asm("mov.b64 %0, {%1, %1};" : "=l"(r) : "r"(__float_as_uint(x)));
    return r;
}

// ---------------- init ----------------
__global__ void k_init(const float* __restrict__ x, const float* __restrict__ pw,
                       const float* __restrict__ pb, const float* __restrict__ rat0) {
    int n = blockIdx.x * blockDim.x + threadIdx.x;
    if (n < NR) {
        int b = n >> 10, l = n & 1023;
        const float* xb = x + (size_t)b * 32768 + l;
        #pragma unroll
        for (int j = 0; j < 4; j++) {
            float acc = pb[j];
            #pragma unroll
            for (int cz = 0; cz < 32; cz++) acc += xb[cz * 1024] * pw[j * 32 + cz];
            g_xt[n * 4 + j] = tanhf(acc);
        }
        g_code[n] = 0.f;
        g_gid[n] = 0;
    }
    if (n < VOC * KL) g_rat[n] = rat0[n];
    if (n < NSTEP * 128) {
        int pos = n >> 7, j = n & 127;
        float inv = powf(10000.f, -(float)(2 * j) / 256.f);
        float ang = (float)pos * inv;
        g_ropetab[n] = make_float2(cosf(ang), sinf(ang));
    }
    if (n == 0) g_uni = 0.f;
}

// ---------------- embed current token ----------------
__global__ void k_embed(const float* __restrict__ in_w, const float* __restrict__ in_b, int step) {
    int idx = blockIdx.x * blockDim.x + threadIdx.x;
    int n = idx >> 8, d = idx & 255;
    g_h[idx] = g_code[n] * in_w[2 * d] + g_xt[n * 4 + step] * in_w[2 * d + 1] + in_b[d];
}

// ---------------- SGEMM: C = A[M,K] @ W[N,K]^T + bias ----------------
// 128x128 tile, 128 threads, 16x8 micro-tile (FFMA2, N-packed accumulators),
// double-buffered smem, rope fused on A loads, 3-way column-split outputs.
__global__ void __launch_bounds__(128, 2) k_gemm(
    const float* __restrict__ A, const float* __restrict__ W,
    const float* __restrict__ bias,
    float* __restrict__ C0, float* __restrict__ C1, float* __restrict__ C2,
    int seg, int N, int K, int relu, int ropeN, const float2* __restrict__ rtab) {
    __shared__ float As[2][16][132];
    __shared__ float Bs[2][16][132];
    const int bm = blockIdx.y * 128;
    const int bn = blockIdx.x * 128;
    const int tid = threadIdx.x;
    const int tx = tid & 15;   // N dir: 16 threads x (4 + 4 split cols)
    const int ty = tid >> 4;   // M dir: 8 threads x (8 + 8 split rows)
    const bool dorope = bn < ropeN;

    unsigned long long acc[16][4];
    #pragma unroll
    for (int m = 0; m < 16; m++)
        #pragma unroll
        for (int p = 0; p < 4; p++) acc[m][p] = 0ull;

    const int nT = K >> 4;
    float4 ra[4], rb[4];

    // prefetch tile 0
    #pragma unroll
    for (int i = 0; i < 4; i++) {
        int idx = tid + i * 128;
        int row = idx >> 2, kq = (idx & 3) << 2;
        ra[i] = *(const float4*)(A + (size_t)(bm + row) * K + kq);
        rb[i] = *(const float4*)(W + (size_t)(bn + row) * K + kq);
    }
    if (dorope) {
        #pragma unroll
        for (int i = 0; i < 4; i++) {
            int idx = tid + i * 128;
            int kq = (idx & 3) << 2;
            int j = kq >> 1;
            float2 cs0 = rtab[j], cs1 = rtab[j + 1];
            float x0 = ra[i].x, y0 = ra[i].y, x1 = ra[i].z, y1 = ra[i].w;
            ra[i].x = x0 * cs0.x - y0 * cs0.y;
            ra[i].y = y0 * cs0.x + x0 * cs0.y;
            ra[i].z = x1 * cs1.x - y1 * cs1.y;
            ra[i].w = y1 * cs1.x + x1 * cs1.y;
        }
    }
    #pragma unroll
    for (int i = 0; i < 4; i++) {
        int idx = tid + i * 128;
        int row = idx >> 2, kq = (idx & 3) << 2;
        As[0][kq + 0][row] = ra[i].x; As[0][kq + 1][row] = ra[i].y;
        As[0][kq + 2][row] = ra[i].z; As[0][kq + 3][row] = ra[i].w;
        Bs[0][kq + 0][row] = rb[i].x; Bs[0][kq + 1][row] = rb[i].y;
        Bs[0][kq + 2][row] = rb[i].z; Bs[0][kq + 3][row] = rb[i].w;
    }
    __syncthreads();

    for (int t = 0; t < nT; t++) {
        const int buf = t & 1;
        if (t + 1 < nT) {
            int k0 = (t + 1) << 4;
            #pragma unroll
            for (int i = 0; i < 4; i++) {
                int idx = tid + i * 128;
                int row = idx >> 2, kq = (idx & 3) << 2;
                ra[i] = *(const float4*)(A + (size_t)(bm + row) * K + k0 + kq);
                rb[i] = *(const float4*)(W + (size_t)(bn + row) * K + k0 + kq);
            }
            if (dorope) {
                #pragma unroll
                for (int i = 0; i < 4; i++) {
                    int idx = tid + i * 128;
                    int kq = (idx & 3) << 2;
                    int j = (k0 + kq) >> 1;
                    float2 cs0 = rtab[j], cs1 = rtab[j + 1];
                    float x0 = ra[i].x, y0 = ra[i].y, x1 = ra[i].z, y1 = ra[i].w;
                    ra[i].x = x0 * cs0.x - y0 * cs0.y;
                    ra[i].y = y0 * cs0.x + x0 * cs0.y;
                    ra[i].z = x1 * cs1.x - y1 * cs1.y;
                    ra[i].w = y1 * cs1.x + x1 * cs1.y;
                }
            }
        }
        #pragma unroll
        for (int kk = 0; kk < 16; kk++) {
            float4 a0 = *(const float4*)&As[buf][kk][ty * 8];
            float4 a1 = *(const float4*)&As[buf][kk][ty * 8 + 4];
            float4 a2 = *(const float4*)&As[buf][kk][64 + ty * 8];
            float4 a3 = *(const float4*)&As[buf][kk][64 + ty * 8 + 4];
            union { float4 v; unsigned long long u[2]; } b0, b1;
            b0.v = *(const float4*)&Bs[buf][kk][tx * 4];
            b1.v = *(const float4*)&Bs[buf][kk][64 + tx * 4];
            unsigned long long bp[4] = {b0.u[0], b0.u[1], b1.u[0], b1.u[1]};
            float av[16] = {a0.x, a0.y, a0.z, a0.w, a1.x, a1.y, a1.z, a1.w,
                            a2.x, a2.y, a2.z, a2.w, a3.x, a3.y, a3.z, a3.w};
            #pragma unroll
            for (int m = 0; m < 16; m++) {
                unsigned long long ad = dup2(av[m]);
                FMA2(acc[m][0], ad, bp[0]);
                FMA2(acc[m][1], ad, bp[1]);
                FMA2(acc[m][2], ad, bp[2]);
                FMA2(acc[m][3], ad, bp[3]);
            }
        }
        if (t + 1 < nT) {
            const int nb = (t + 1) & 1;
            #pragma unroll
            for (int i = 0; i < 4; i++) {
                int idx = tid + i * 128;
                int row = idx >> 2, kq = (idx & 3) << 2;
                As[nb][kq + 0][row] = ra[i].x; As[nb][kq + 1][row] = ra[i].y;
                As[nb][kq + 2][row] = ra[i].z; As[nb][kq + 3][row] = ra[i].w;
                Bs[nb][kq + 0][row] = rb[i].x; Bs[nb][kq + 1][row] = rb[i].y;
                Bs[nb][kq + 2][row] = rb[i].z; Bs[nb][kq + 3][row] = rb[i].w;
            }
        }
        __syncthreads();
    }

    // epilogue: rows ty*8 + (m<8 ? m : 64+m-8), cols tx*4 + half*64
    #pragma unroll
    for (int m = 0; m < 16; m++) {
        int row = bm + ((m < 8) ? (ty * 8 + m) : (64 + ty * 8 + m - 8));
        #pragma unroll
        for (int p = 0; p < 4; p++) {
            int half = p >> 1;
            int col = bn + half * 64 + tx * 4 + (p & 1) * 2;
            union { unsigned long long u; float2 f; } v;
            v.u = acc[m][p];
            v.f.x += bias[col];
            v.f.y += bias[col + 1];
            if (relu) { v.f.x = fmaxf(v.f.x, 0.f); v.f.y = fmaxf(v.f.y, 0.f); }
            int s = col / seg;
            float* Cp = (s == 0) ? C0 : ((s == 1) ? C1 : C2);
            *(float2*)(Cp + (size_t)row * seg + (col - s * seg)) = v.f;
        }
    }
}

// ---------------- attention over cached K/V ----------------
__global__ void k_attn(int l, int npos) {
    int n = blockIdx.x;
    int lane = threadIdx.x & 31;
    int col = (threadIdx.x >> 5) * 32 + lane;
    float q = g_qbuf[(size_t)n * DM + col];
    float s[4];
    float m = -1e30f;
    #pragma unroll
    for (int j = 0; j < 4; j++) {
        if (j < npos) {
            float kv = g_kc[((size_t)(l * NSTEP + j) * NR + n) * DM + col];
            float prod = q * kv;
            #pragma unroll
            for (int o = 16; o > 0; o >>= 1) prod += __shfl_xor_sync(0xffffffffu, prod, o);
            s[j] = prod / sqrtf(32.f);
            m = fmaxf(m, s[j]);
        }
    }
    float den = 0.f, o = 0.f;
    #pragma unroll
    for (int j = 0; j < 4; j++) {
        if (j < npos) {
            float p = expf(s[j] - m);
            den += p;
            o += p * g_vc[((size_t)(l * NSTEP + j) * NR + n) * DM + col];
        }
    }
    g_attno[(size_t)n * DM + col] = o / den;
}

// ---------------- residual + layernorm ----------------
__global__ void k_ln(const float* __restrict__ delta, const float* __restrict__ gg,
                     const float* __restrict__ bb) {
    int warp = threadIdx.x >> 5, lane = threadIdx.x & 31;
    int n = blockIdx.x * 8 + warp;
    float v[8];
    float sum = 0.f;
    #pragma unroll
    for (int k = 0; k < 8; k++) {
        int c = k * 32 + lane;
        v[k] = g_h[(size_t)n * DM + c] + delta[(size_t)n * DM + c];
        sum += v[k];
    }
    #pragma unroll
    for (int o = 16; o > 0; o >>= 1) sum += __shfl_xor_sync(0xffffffffu, sum, o);
    float mu = sum / 256.f;
    float var = 0.f;
    #pragma unroll
    for (int k = 0; k < 8; k++) { float d = v[k] - mu; var += d * d; }
    #pragma unroll
    for (int o = 16; o > 0; o >>= 1) var += __shfl_xor_sync(0xffffffffu, var, o);
    var /= 256.f;
    float inv = 1.f / sqrtf(var + 1e-5f);
    #pragma unroll
    for (int k = 0; k < 8; k++) {
        int c = k * 32 + lane;
        g_h[(size_t)n * DM + c] = (v[k] - mu) * inv * gg[c] + bb[c];
    }
}

// ---------------- out projection (N x 9) ----------------
__global__ void k_outproj(const float* __restrict__ out_w, const float* __restrict__ out_b) {
    int warp = threadIdx.x >> 5, lane = threadIdx.x & 31;
    int n = blockIdx.x * 8 + warp;
    float hv[8];
    #pragma unroll
    for (int k = 0; k < 8; k++) hv[k] = g_h[(size_t)n * DM + k * 32 + lane];
    #pragma unroll
    for (int j = 0; j < 9; j++) {
        float acc = 0.f;
        #pragma unroll
        for (int k = 0; k < 8; k++) acc += hv[k] * out_w[j * DM + k * 32 + lane];
        #pragma unroll
        for (int o = 16; o > 0; o >>= 1) acc += __shfl_xor_sync(0xffffffffu, acc, o);
        if (lane == 0) g_z[n * 9 + j] = acc + out_b[j];
    }
}

// ---------------- min/max ----------------
__global__ void k_mm_init() { g_mm[0] = 0xFFFFFFFFu; g_mm[1] = 0u; }

__global__ void k_minmax() {
    __shared__ unsigned smn[256], smx[256];
    int t = threadIdx.x;
    unsigned mn = 0xFFFFFFFFu, mx = 0u;
    for (int n = blockIdx.x * 256 + t; n < NR; n += gridDim.x * 256) {
        unsigned e = f2u(g_z[n * 9]);
        mn = (e < mn) ? e : mn;
        mx = (e > mx) ? e : mx;
    }
    smn[t] = mn; smx[t] = mx;
    __syncthreads();
    for (int s = 128; s > 0; s >>= 1) {
        if (t < s) {
            smn[t] = (smn[t + s] < smn[t]) ? smn[t + s] : smn[t];
            smx[t] = (smx[t + s] > smx[t]) ? smx[t + s] : smx[t];
        }
        __syncthreads();
    }
    if (t == 0) { atomicMin(&g_mm[0], smn[0]); atomicMax(&g_mm[1], smx[0]); }
}

// ---------------- bin assignment ----------------
__global__ void k_bins(int step) {
    int n = blockIdx.x * blockDim.x + threadIdx.x;
    float MN = u2f(g_mm[0]);
    float MX = u2f(g_mm[1]);
    float x = g_z[n * 9];
    float bb[7];
    #pragma unroll
    for (int j = 0; j < 7; j++) bb[j] = g_z[n * 9 + 1 + j];
    int bin = -1;
    float xq = 0.f;
    #pragma unroll
    for (int j = 0; j < 8; j++) {
        float l = (j == 0) ? MN - 0.01f : bb[j - 1];
        float r = (j == 7) ? MX + 0.01f : bb[j];
        if (bin < 0 && x >= l && x < r && r > l) { bin = j; xq = (l + r) * 0.5f; }
    }
    g_bin[n] = bin;
    g_zarr[step * NR + n] = x;
    g_qarr[step * NR + n] = xq;
}

// ---------------- histogram ----------------
__global__ void k_histzero() {
    int i = blockIdx.x * blockDim.x + threadIdx.x;
    if (i < VOC * KL) g_Hc[i] = 0.f;
    else if (i < VOC * KL + VOC) g_Hm1[i - VOC * KL] = 0.f;
}

__global__ void k_hist() {
    int n = blockIdx.x * 256 + threadIdx.x;
    int g = g_gid[n];
    if (g < 0 || g >= VOC) return;
    int bin = g_bin[n];
    if (bin >= 0) atomicAdd(&g_Hc[g * KL + bin], 1.f);
    else atomicAdd(&g_Hm1[g], 1.f);
}

// ---------------- ratios update ----------------
__global__ void k_ratupd() {
    int v = blockIdx.x * 256 + threadIdx.x;
    #pragma unroll
    for (int k = 0; k < 7; k++) {
        float hc = g_Hc[v * KL + k];
        if (hc > 0.f) g_rat[v * KL + k] = hc;
    }
    float hc7 = g_Hc[v * KL + 7], hm = g_Hm1[v], old7 = g_rat[v * KL + 7];
    g_rat[v * KL + 7] = hc7 > 0.f ? hc7 : (hm > 0.f ? hm : old7);
}

// ---------------- grad dot + order clip ----------------
__global__ void __launch_bounds__(256) k_grad(int step) {
    __shared__ float sd[256], sc[256];
    int t = threadIdx.x;
    int n = blockIdx.x * 256 + t;
    int g = g_gid[n];
    g = g < 0 ? 0 : (g > VOC - 1 ? VOC - 1 : g);
    float r[8];
    #pragma unroll
    for (int k = 0; k < 8; k++) r[k] = g_rat[g * KL + k];
    float gr[7];
    float nrm = 0.f;
    #pragma unroll
    for (int k = 0; k < 7; k++) { gr[k] = -(r[k + 1] - r[k]); nrm += gr[k] * gr[k]; }
    nrm = sqrtf(nrm);
    float bby[7];
    #pragma unroll
    for (int k = 0; k < 7; k++) bby[k] = g_z[n * 9 + 1 + k];
    float dot = 0.f;
    #pragma unroll
    for (int k = 0; k < 7; k++) dot += bby[k] * (gr[k] / nrm);
    float cl = 0.f;
    #pragma unroll
    for (int k = 0; k < 6; k++) {
        float d = bby[k + 1] - bby[k];
        d = fmaxf(d, -9999999.f);
        d = fminf(d, 0.1f);
        cl += d;
    }
    int bin = g_bin[n];
    g_gid[n] += bin * (1 << (3 * step));
    g_code[n] = (float)bin;
    sd[t] = dot; sc[t] = cl;
    __syncthreads();
    for (int s = 128; s > 0; s >>= 1) {
        if (t < s) { sd[t] += sd[t + s]; sc[t] += sc[t + s]; }
        __syncthreads();
    }
    if (t == 0) { g_pdot[blockIdx.x] = sd[0]; g_pclip[blockIdx.x] = sc[0]; }
}

__global__ void k_losses() {
    __shared__ float sd[128], sc[128];
    int t = threadIdx.x;
    sd[t] = g_pdot[t]; sc[t] = g_pclip[t];
    __syncthreads();
    for (int s = 64; s > 0; s >>= 1) {
        if (t < s) { sd[t] += sd[t + s]; sc[t] += sc[t + s]; }
        __syncthreads();
    }
    if (t == 0) g_uni += sd[0] / (float)NR - sc[0] / ((float)NR * 6.f);
}

// ---------------- vq loss partials ----------------
__global__ void k_vqpart() {
    __shared__ float s[256];
    int t = threadIdx.x;
    int n = blockIdx.x * 256 + t;
    float acc = 0.f;
    #pragma unroll
    for (int j = 0; j < NSTEP; j++) {
        float d = g_qarr[j * NR + n] - g_zarr[j * NR + n];
        acc += d * d;
    }
    s[t] = acc;
    __syncthreads();
    for (int r = 128; r > 0; r >>= 1) {
        if (t < r) s[t] += s[t + r];
        __syncthreads();
    }
    if (t == 0) g_pvq[blockIdx.x] = s[0];
}

// ---------------- final projection ----------------
__global__ void k_zq(const float* __restrict__ ppw, const float* __restrict__ ppb,
                     float* __restrict__ out) {
    int t = blockIdx.x * blockDim.x + threadIdx.x;
    int b = t >> 15;
    int rem = t & 32767;
    int cz = rem >> 10;
    int l = rem & 1023;
    int n = (b << 10) + l;
    float acc = ppb[cz];
    #pragma unroll
    for (int j = 0; j < 4; j++) {
        float q = g_qarr[j * NR + n], z = g_zarr[j * NR + n];
        float s = (q + z) - z;
        acc += s * ppw[cz * 4 + j];
    }
    out[t] = acc;
}

__global__ void k_scalars(float* __restrict__ out, int out_size) {
    __shared__ float s[128];
    int t = threadIdx.x;
    s[t] = g_pvq[t];
    __syncthreads();
    for (int r = 64; r > 0; r >>= 1) {
        if (t < r) s[t] += s[t + r];
        __syncthreads();
    }
    if (t == 0) {
        out[out_size - 2] = s[0] / (float)(NR * NSTEP);
        out[out_size - 1] = g_uni;
    }
}

// ---------------- host ----------------
static void gemm(const float* A, const float* W, const float* bias,
                 float* C0, float* C1, float* C2, int seg,
                 int N, int K, int relu, int ropeN, const float2* rtab) {
    dim3 grid(N / 128, NR / 128);
    k_gemm<<<grid, 128>>>(A, W, bias, C0, C1, C2, seg, N, K, relu, ropeN, rtab);
}

extern "C" void kernel_launch(void* const* d_in, const int* in_sizes, int n_in,
                              void* d_out, int out_size) {
    const float* x     = (const float*)d_in[0];
    const float* ppvw  = (const float*)d_in[1];
    const float* ppvb  = (const float*)d_in[2];
    const float* ppow  = (const float*)d_in[3];
    const float* ppob  = (const float*)d_in[4];
    const float* in_w  = (const float*)d_in[5];
    const float* in_b  = (const float*)d_in[6];
    const float* out_w = (const float*)d_in[7];
    const float* out_b = (const float*)d_in[8];
    const float* qkv_w = (const float*)d_in[9];
    const float* qkv_b = (const float*)d_in[10];
    const float* ao_w  = (const float*)d_in[11];
    const float* ao_b  = (const float*)d_in[12];
    const float* f1_w  = (const float*)d_in[13];
    const float* f1_b  = (const float*)d_in[14];
    const float* f2_w  = (const float*)d_in[15];
    const float* f2_b  = (const float*)d_in[16];
    const float* ln1g  = (const float*)d_in[17];
    const float* ln1b  = (const float*)d_in[18];
    const float* ln2g  = (const float*)d_in[19];
    const float* ln2b  = (const float*)d_in[20];
    const float* rat0  = (const float*)d_in[21];
    float* out = (float*)d_out;

    float *h, *qb, *at_o, *d1, *d2, *kc, *vc;
    float2* rtab;
    cudaGetSymbolAddress((void**)&h,    g_h);
    cudaGetSymbolAddress((void**)&qb,   g_qbuf);
    cudaGetSymbolAddress((void**)&at_o, g_attno);
    cudaGetSymbolAddress((void**)&d1,   g_d1);
    cudaGetSymbolAddress((void**)&d2,   g_d2);
    cudaGetSymbolAddress((void**)&kc,   g_kc);
    cudaGetSymbolAddress((void**)&vc,   g_vc);
    cudaGetSymbolAddress((void**)&rtab, g_ropetab);

    k_init<<<NR / 256, 256>>>(x, ppvw, ppvb, rat0);

    for (int i = 0; i < NSTEP; i++) {
        k_embed<<<NR * DM / 256, 256>>>(in_w, in_b, i);
        for (int l = 0; l < NLAY; l++) {
            const float* Wl = qkv_w + (size_t)l * 768 * DM;
            const float* bl = qkv_b + l * 768;
            float* kslot = kc + (size_t)(l * NSTEP + i) * NR * DM;
            float* vslot = vc + (size_t)(l * NSTEP + i) * NR * DM;
            // fused QKV: N=768, rope on A for cols [0,512), split outputs
            gemm(h, Wl, bl, qb, kslot, vslot, 256, 768, DM, 0, 512, rtab + i * 128);
            k_attn<<<NR, 256>>>(l, i + 1);
            gemm(at_o, ao_w + (size_t)l * DM * DM, ao_b + l * DM,
                 d1, nullptr, nullptr, DM, DM, DM, 0, 0, rtab);
            k_ln<<<NR / 8, 256>>>(d1, ln1g + l * DM, ln1b + l * DM);
            gemm(h, f1_w + (size_t)l * FFD * DM, f1_b + l * FFD,
                 d2, nullptr, nullptr, FFD, FFD, DM, 1, 0, rtab);
            gemm(d2, f2_w + (size_t)l * DM * FFD, f2_b + l * DM,
                 d1, nullptr, nullptr, DM, DM, FFD, 0, 0, rtab);
            k_ln<<<NR / 8, 256>>>(d1, ln2g + l * DM, ln2b + l * DM);
        }
        k_outproj<<<NR / 8, 256>>>(out_w, out_b);
        k_mm_init<<<1, 1>>>();
        k_minmax<<<64, 256>>>();
        k_bins<<<NR / 256, 256>>>(i);
        k_histzero<<<(VOC * KL + VOC + 255) / 256, 256>>>();
        k_hist<<<NR / 256, 256>>>();
        k_ratupd<<<VOC / 256, 256>>>();
        k_grad<<<128, 256>>>(i);
        k_losses<<<1, 128>>>();
    }

    k_vqpart<<<128, 256>>>();
    k_zq<<<(NR * 32) / 256, 256>>>(ppow, ppob, out);
    k_scalars<<<1, 128>>>(out, out_size);
}